// round 11
// baseline (speedup 1.0000x reference)
#include <cuda_runtime.h>
#include <cstdint>

#define S_DIM 16
#define M_DIM 768
#define N_DIM 1024
#define ROWS_PER_BLK 2
#define STAGE_ROWS 3              // exactly y0(ybase) .. y0(ybase+1)+1
#define LPAD 68                   // covers x0 >= -65
#define RPAD 4
#define RSTRIDE (LPAD + N_DIM + RPAD)   // 1096 floats = 4384 B
#define ROW_BYTES (N_DIM * 4)     // 4096
#define VEC_PER_ROW (RSTRIDE / 4)       // 274 float4 per padded row
#define B2F_OFF (STAGE_ROWS * RSTRIDE)  // float offset of interleaved blend region
#define B2_ROW_FLOATS (2 * RSTRIDE)     // 2192 floats (1096 float2) per blended row
#define INVALID_VAL 100.0f

__device__ __forceinline__ uint32_t smem_u32(const void* p) {
    return (uint32_t)__cvta_generic_to_shared(p);
}

__global__ __launch_bounds__(256) void lr_distance_kernel(
    const float* __restrict__ lr,
    const float* __restrict__ rl,
    float* __restrict__ out)
{
    // 3 staged rows (13152 B) + 2 interleaved blended rows (17536 B) = 30688 B
    __shared__ __align__(16) float sm[STAGE_ROWS * RSTRIDE + ROWS_PER_BLK * B2_ROW_FLOATS];
    __shared__ __align__(8)  uint64_t mbar;

    const int tid   = threadIdx.x;
    const int bid   = blockIdx.x;
    const int s     = bid / (M_DIM / ROWS_PER_BLK);
    const int grp   = bid % (M_DIM / ROWS_PER_BLK);
    const int ybase = grp * ROWS_PER_BLK;
    // y0(y) = y-1 for y <= M/2-1, y for y >= M/2  (iy = y*M/(M-1) - 0.5)
    const int g0    = ybase - (ybase < (M_DIM / 2) ? 1 : 0);  // first staged row

    const float* __restrict__ img = rl + s * (M_DIM * N_DIM);
    const uint32_t bar = smem_u32(&mbar);

    // Thread 0: init barrier, proxy-fence, then issue bulk copies (all program-ordered).
    // No block barrier needed before TMA issue — other threads only touch disjoint smem
    // until the pads __syncthreads below, which also publishes the init to them.
    if (tid == 0) {
        asm volatile("mbarrier.init.shared.b64 [%0], %1;" :: "r"(bar), "r"(1) : "memory");
        asm volatile("fence.proxy.async.shared::cta;" ::: "memory");
        int n_valid = 0;
        #pragma unroll
        for (int r = 0; r < STAGE_ROWS; r++) {
            int g = g0 + r;
            if (g >= 0 && g < M_DIM) n_valid++;
        }
        asm volatile("mbarrier.arrive.expect_tx.shared.b64 _, [%0], %1;"
                     :: "r"(bar), "r"(n_valid * ROW_BYTES) : "memory");
        #pragma unroll
        for (int r = 0; r < STAGE_ROWS; r++) {
            int g = g0 + r;
            if (g >= 0 && g < M_DIM) {
                uint32_t dst = smem_u32(sm + r * RSTRIDE + LPAD);
                const float* src = img + g * N_DIM;
                asm volatile(
                    "cp.async.bulk.shared::cta.global.mbarrier::complete_tx::bytes "
                    "[%0], [%1], %2, [%3];"
                    :: "r"(dst), "l"(src), "r"(ROW_BYTES), "r"(bar) : "memory");
            }
        }
    }

    // Zero staged-row pads (72 floats/row, disjoint from TMA destinations)
    for (int v = tid; v < STAGE_ROWS * (LPAD + RPAD); v += 256) {
        int r = v / (LPAD + RPAD);
        int p = v % (LPAD + RPAD);
        int idx = (p < LPAD) ? p : (LPAD + N_DIM + (p - LPAD));
        sm[r * RSTRIDE + idx] = 0.0f;
    }
    // Zero out-of-bounds staged rows (only first/last group of each image)
    #pragma unroll
    for (int r = 0; r < STAGE_ROWS; r++) {
        int g = g0 + r;
        if (g < 0 || g >= M_DIM) {
            for (int c = tid; c < N_DIM / 4; c += 256)
                reinterpret_cast<float4*>(sm + r * RSTRIDE + LPAD)[c] =
                    make_float4(0.0f, 0.0f, 0.0f, 0.0f);
        }
    }
    __syncthreads();   // publishes pad stores + mbarrier init to all threads

    // Wait for the bulk copies (acquire orders subsequent LDS after TMA writes)
    {
        uint32_t done;
        do {
            asm volatile(
                "{\n\t.reg .pred p;\n\t"
                "mbarrier.try_wait.parity.acquire.cta.shared::cta.b64 p, [%1], %2;\n\t"
                "selp.b32 %0, 1, 0, p;\n\t}"
                : "=r"(done) : "r"(bar), "r"(0u) : "memory");
        } while (!done);
    }

    // ── Vertical pre-blend into PAIR-INTERLEAVED buffer: B2[i] = (b[i], b[i+1]) ──
    #pragma unroll
    for (int r = 0; r < ROWS_PER_BLK; r++) {
        const int y = ybase + r;
        float yl  = 2.0f * (float)y / (float)(M_DIM - 1) - 1.0f;
        float iy  = ((yl + 1.0f) * (float)M_DIM - 1.0f) * 0.5f;
        float y0f = floorf(iy);
        float wy1 = iy - y0f;
        int   r0  = (int)y0f - g0;               // in [0, 1]

        const float*  __restrict__ af = sm + r0 * RSTRIDE;
        const float*  __restrict__ bf = sm + (r0 + 1) * RSTRIDE;
        const float4* __restrict__ a4 = reinterpret_cast<const float4*>(af);
        const float4* __restrict__ b4 = reinterpret_cast<const float4*>(bf);
        float4* __restrict__ dst4 =
            reinterpret_cast<float4*>(sm + B2F_OFF + r * B2_ROW_FLOATS);

        #pragma unroll
        for (int c0 = 0; c0 < VEC_PER_ROW; c0 += 256) {
            int c  = c0 + tid;
            int cc = min(c, VEC_PER_ROW - 1);
            float4 va = a4[cc], vb = b4[cc], o;
            o.x = fmaf(wy1, vb.x - va.x, va.x);
            o.y = fmaf(wy1, vb.y - va.y, va.y);
            o.z = fmaf(wy1, vb.z - va.z, va.z);
            o.w = fmaf(wy1, vb.w - va.w, va.w);

            // next element blend[4c+4]: from right neighbor lane, else scalar fallback
            float n = __shfl_down_sync(0xffffffffu, o.x, 1);
            bool n_ok = ((tid & 31) != 31) && (c + 1 < VEC_PER_ROW);
            if (!n_ok) {
                int e = 4 * cc + 4;
                if (e < RSTRIDE) {
                    float aa = af[e], bb = bf[e];
                    n = fmaf(wy1, bb - aa, aa);
                } else {
                    n = o.w;   // pair B2[RSTRIDE-1] is never gathered
                }
            }

            if (c < VEC_PER_ROW) {
                dst4[2 * c]     = make_float4(o.x, o.y, o.y, o.z);
                dst4[2 * c + 1] = make_float4(o.z, o.w, o.w, n);
            }
        }
    }
    __syncthreads();

    // ── Gather: ONE random LDS.64 per element from the interleaved blended row ──
    const int   xs    = tid * 4;
    const float xlb   = (float)xs;
    const int   sbase = s * (M_DIM * N_DIM);
    const float RCP_SCALE = 2.0f / 1023.0f;

    #pragma unroll
    for (int r = 0; r < ROWS_PER_BLK; r++) {
        const int y = ybase + r;
        const float2* __restrict__ rowb =
            reinterpret_cast<const float2*>(sm + B2F_OFF + r * B2_ROW_FLOATS);

        float4 dv = *reinterpret_cast<const float4*>(lr + sbase + y * N_DIM + xs);
        float dd[4] = {dv.x, dv.y, dv.z, dv.w};
        float res[4];

        #pragma unroll
        for (int j = 0; j < 4; j++) {
            float d  = dd[j];
            float xr = (xlb + (float)j) - d;

            float t   = fmaf(xr, RCP_SCALE, -1.0f);   // xr_normed
            float ix  = fmaf(t, 512.0f, 511.5f);      // ((t+1)*1024 - 1)*0.5
            float x0f = floorf(ix);
            float wx1 = ix - x0f;
            int   idx = (int)x0f + LPAD;              // in [3, 1092]; pads absorb OOB

            float2 v = rowb[idx];                     // (blend[idx], blend[idx+1])
            float warped = fmaf(wx1, v.y - v.x, v.x);

            float dist = fabsf(d + warped);
            // d in [0,64) => xr <= 1023 < N always; only left OOB can occur
            res[j] = (xr < 0.0f) ? INVALID_VAL : dist;
        }

        *reinterpret_cast<float4*>(out + sbase + y * N_DIM + xs) =
            make_float4(res[0], res[1], res[2], res[3]);
    }
}

extern "C" void kernel_launch(void* const* d_in, const int* in_sizes, int n_in,
                              void* d_out, int out_size)
{
    const float* lr = (const float*)d_in[0];
    const float* rl = (const float*)d_in[1];
    float* out = (float*)d_out;

    int blocks = S_DIM * (M_DIM / ROWS_PER_BLK);   // 16 * 384 = 6144
    lr_distance_kernel<<<blocks, 256>>>(lr, rl, out);
}

// round 12
// speedup vs baseline: 1.0811x; 1.0811x over previous
#include <cuda_runtime.h>
#include <cstdint>

#define S_DIM 16
#define M_DIM 768
#define N_DIM 1024
#define ROWS_PER_BLK 2
#define STAGE_ROWS 3              // exactly y0(ybase) .. y0(ybase+1)+1
#define LPAD 68                   // covers x0 >= -65
#define RPAD 4
#define RSTRIDE (LPAD + N_DIM + RPAD)   // 1096 floats = 4384 B
#define ROW_BYTES (N_DIM * 4)     // 4096
#define BL_OFF (STAGE_ROWS * RSTRIDE)   // blend buffer base (floats)
#define VEC_PER_ROW (RSTRIDE / 4)       // 274 float4 per padded row
#define INVALID_VAL 100.0f

__device__ __forceinline__ uint32_t smem_u32(const void* p) {
    return (uint32_t)__cvta_generic_to_shared(p);
}

__global__ __launch_bounds__(256) void lr_distance_kernel(
    const float* __restrict__ lr,
    const float* __restrict__ rl,
    float* __restrict__ out)
{
    // 3 staged rows + 2 blended rows = 5 * 4384 B = 21920 B
    __shared__ __align__(16) float sm[(STAGE_ROWS + ROWS_PER_BLK) * RSTRIDE];
    __shared__ __align__(8)  uint64_t mbar;

    const int tid   = threadIdx.x;
    const int bid   = blockIdx.x;
    const int s     = bid / (M_DIM / ROWS_PER_BLK);
    const int grp   = bid % (M_DIM / ROWS_PER_BLK);
    const int ybase = grp * ROWS_PER_BLK;
    // y0(y) = y-1 for y <= M/2-1, y for y >= M/2  (iy = y*M/(M-1) - 0.5)
    const int g0    = ybase - (ybase < (M_DIM / 2) ? 1 : 0);  // first staged row

    const float* __restrict__ img = rl + s * (M_DIM * N_DIM);
    const uint32_t bar = smem_u32(&mbar);

    // Thread 0: init barrier, proxy-fence, issue bulk copies — all program-ordered
    // within one thread. Other threads only write disjoint pad regions before the
    // pads __syncthreads below, which also publishes the init before anyone waits.
    if (tid == 0) {
        asm volatile("mbarrier.init.shared.b64 [%0], %1;" :: "r"(bar), "r"(1) : "memory");
        asm volatile("fence.proxy.async.shared::cta;" ::: "memory");
        int n_valid = 0;
        #pragma unroll
        for (int r = 0; r < STAGE_ROWS; r++) {
            int g = g0 + r;
            if (g >= 0 && g < M_DIM) n_valid++;
        }
        asm volatile("mbarrier.arrive.expect_tx.shared.b64 _, [%0], %1;"
                     :: "r"(bar), "r"(n_valid * ROW_BYTES) : "memory");
        #pragma unroll
        for (int r = 0; r < STAGE_ROWS; r++) {
            int g = g0 + r;
            if (g >= 0 && g < M_DIM) {
                uint32_t dst = smem_u32(sm + r * RSTRIDE + LPAD);
                const float* src = img + g * N_DIM;
                asm volatile(
                    "cp.async.bulk.shared::cta.global.mbarrier::complete_tx::bytes "
                    "[%0], [%1], %2, [%3];"
                    :: "r"(dst), "l"(src), "r"(ROW_BYTES), "r"(bar) : "memory");
            }
        }
    }

    // Zero staged-row pads (72 floats/row, disjoint from TMA destinations)
    for (int v = tid; v < STAGE_ROWS * (LPAD + RPAD); v += 256) {
        int r = v / (LPAD + RPAD);
        int p = v % (LPAD + RPAD);
        int idx = (p < LPAD) ? p : (LPAD + N_DIM + (p - LPAD));
        sm[r * RSTRIDE + idx] = 0.0f;
    }
    // Zero out-of-bounds staged rows (only first/last group of each image)
    #pragma unroll
    for (int r = 0; r < STAGE_ROWS; r++) {
        int g = g0 + r;
        if (g < 0 || g >= M_DIM) {
            for (int c = tid; c < N_DIM / 4; c += 256)
                reinterpret_cast<float4*>(sm + r * RSTRIDE + LPAD)[c] =
                    make_float4(0.0f, 0.0f, 0.0f, 0.0f);
        }
    }
    __syncthreads();   // publishes pad stores + mbarrier init to all threads

    // Wait for the bulk copies (acquire orders subsequent LDS after TMA writes)
    {
        uint32_t done;
        do {
            asm volatile(
                "{\n\t.reg .pred p;\n\t"
                "mbarrier.try_wait.parity.acquire.cta.shared::cta.b64 p, [%1], %2;\n\t"
                "selp.b32 %0, 1, 0, p;\n\t}"
                : "=r"(done) : "r"(bar), "r"(0u) : "memory");
        } while (!done);
    }

    // ── Vertical pre-blend: one padded row per output row, fully vectorized ──
    #pragma unroll
    for (int r = 0; r < ROWS_PER_BLK; r++) {
        const int y = ybase + r;
        float yl  = 2.0f * (float)y / (float)(M_DIM - 1) - 1.0f;
        float iy  = ((yl + 1.0f) * (float)M_DIM - 1.0f) * 0.5f;
        float y0f = floorf(iy);
        float wy1 = iy - y0f;
        int   r0  = (int)y0f - g0;               // in [0, 1]

        const float4* __restrict__ a = reinterpret_cast<const float4*>(sm + r0 * RSTRIDE);
        const float4* __restrict__ b = reinterpret_cast<const float4*>(sm + (r0 + 1) * RSTRIDE);
        float4* __restrict__ dst = reinterpret_cast<float4*>(sm + BL_OFF + r * RSTRIDE);

        for (int c = tid; c < VEC_PER_ROW; c += 256) {
            float4 va = a[c], vb = b[c], o;
            o.x = fmaf(wy1, vb.x - va.x, va.x);
            o.y = fmaf(wy1, vb.y - va.y, va.y);
            o.z = fmaf(wy1, vb.z - va.z, va.z);
            o.w = fmaf(wy1, vb.w - va.w, va.w);
            dst[c] = o;
        }
    }
    __syncthreads();

    // ── Gather: 2 random scalar taps per element from the blended row ──
    const int   xs    = tid * 4;
    const float xlb   = (float)xs;
    const int   sbase = s * (M_DIM * N_DIM);
    const float RCP_SCALE = 2.0f / 1023.0f;

    #pragma unroll
    for (int r = 0; r < ROWS_PER_BLK; r++) {
        const int y = ybase + r;
        const float* __restrict__ rowb = sm + BL_OFF + r * RSTRIDE;

        float4 dv = *reinterpret_cast<const float4*>(lr + sbase + y * N_DIM + xs);
        float dd[4] = {dv.x, dv.y, dv.z, dv.w};
        float res[4];

        #pragma unroll
        for (int j = 0; j < 4; j++) {
            float d  = dd[j];
            float xr = (xlb + (float)j) - d;

            float t   = fmaf(xr, RCP_SCALE, -1.0f);   // xr_normed
            float ix  = fmaf(t, 512.0f, 511.5f);      // ((t+1)*1024 - 1)*0.5
            float x0f = floorf(ix);
            float wx1 = ix - x0f;
            int   idx = (int)x0f + LPAD;              // in [3, 1092]; pads absorb OOB

            float b0 = rowb[idx];
            float b1 = rowb[idx + 1];
            float warped = fmaf(wx1, b1 - b0, b0);

            float dist = fabsf(d + warped);
            // d in [0,64) => xr = x-d <= 1023 < N always; only left OOB possible
            res[j] = (xr < 0.0f) ? INVALID_VAL : dist;
        }

        *reinterpret_cast<float4*>(out + sbase + y * N_DIM + xs) =
            make_float4(res[0], res[1], res[2], res[3]);
    }
}

extern "C" void kernel_launch(void* const* d_in, const int* in_sizes, int n_in,
                              void* d_out, int out_size)
{
    const float* lr = (const float*)d_in[0];
    const float* rl = (const float*)d_in[1];
    float* out = (float*)d_out;

    int blocks = S_DIM * (M_DIM / ROWS_PER_BLK);   // 16 * 384 = 6144
    lr_distance_kernel<<<blocks, 256>>>(lr, rl, out);
}

// round 13
// speedup vs baseline: 1.2264x; 1.1344x over previous
#include <cuda_runtime.h>
#include <cstdint>

#define S_DIM 16
#define M_DIM 768
#define N_DIM 1024
#define ROWS_PER_BLK 2
#define STAGE_ROWS 3              // exactly y0(ybase) .. y0(ybase+1)+1
#define LPAD 68                   // covers x0 >= -65
#define RPAD 4
#define RSTRIDE (LPAD + N_DIM + RPAD)   // 1096 floats = 4384 B
#define ROW_BYTES (N_DIM * 4)     // 4096
#define LR_OFF (STAGE_ROWS * RSTRIDE)           // lr staging (2 x 1024 floats)
#define BL_OFF (LR_OFF + ROWS_PER_BLK * N_DIM)  // blend buffer base
#define VEC_PER_ROW (RSTRIDE / 4)       // 274 float4 per padded row
#define INVALID_VAL 100.0f

__device__ __forceinline__ uint32_t smem_u32(const void* p) {
    return (uint32_t)__cvta_generic_to_shared(p);
}

__global__ __launch_bounds__(256) void lr_distance_kernel(
    const float* __restrict__ lr,
    const float* __restrict__ rl,
    float* __restrict__ out)
{
    // 3 staged rl rows + 2 lr rows + 2 blended rows = 30112 B -> 7 blocks/SM (56 warps)
    __shared__ __align__(16) float sm[STAGE_ROWS * RSTRIDE + ROWS_PER_BLK * N_DIM
                                      + ROWS_PER_BLK * RSTRIDE];
    __shared__ __align__(8)  uint64_t mbar;

    const int tid   = threadIdx.x;
    const int bid   = blockIdx.x;
    const int s     = bid / (M_DIM / ROWS_PER_BLK);
    const int grp   = bid % (M_DIM / ROWS_PER_BLK);
    const int ybase = grp * ROWS_PER_BLK;
    // y0(y) = y-1 for y <= M/2-1, y for y >= M/2  (iy = y*M/(M-1) - 0.5)
    const int g0    = ybase - (ybase < (M_DIM / 2) ? 1 : 0);  // first staged row

    const int sbase = s * (M_DIM * N_DIM);
    const float* __restrict__ img = rl + sbase;
    const uint32_t bar = smem_u32(&mbar);

    // Thread 0: init barrier, proxy-fence, issue all bulk copies (program-ordered).
    if (tid == 0) {
        asm volatile("mbarrier.init.shared.b64 [%0], %1;" :: "r"(bar), "r"(1) : "memory");
        asm volatile("fence.proxy.async.shared::cta;" ::: "memory");
        int n_valid = 0;
        #pragma unroll
        for (int r = 0; r < STAGE_ROWS; r++) {
            int g = g0 + r;
            if (g >= 0 && g < M_DIM) n_valid++;
        }
        asm volatile("mbarrier.arrive.expect_tx.shared.b64 _, [%0], %1;"
                     :: "r"(bar), "r"((n_valid + ROWS_PER_BLK) * ROW_BYTES) : "memory");
        // rl rows (padded destinations)
        #pragma unroll
        for (int r = 0; r < STAGE_ROWS; r++) {
            int g = g0 + r;
            if (g >= 0 && g < M_DIM) {
                uint32_t dst = smem_u32(sm + r * RSTRIDE + LPAD);
                const float* src = img + g * N_DIM;
                asm volatile(
                    "cp.async.bulk.shared::cta.global.mbarrier::complete_tx::bytes "
                    "[%0], [%1], %2, [%3];"
                    :: "r"(dst), "l"(src), "r"(ROW_BYTES), "r"(bar) : "memory");
            }
        }
        // lr rows (dense destinations)
        #pragma unroll
        for (int r = 0; r < ROWS_PER_BLK; r++) {
            uint32_t dst = smem_u32(sm + LR_OFF + r * N_DIM);
            const float* src = lr + sbase + (ybase + r) * N_DIM;
            asm volatile(
                "cp.async.bulk.shared::cta.global.mbarrier::complete_tx::bytes "
                "[%0], [%1], %2, [%3];"
                :: "r"(dst), "l"(src), "r"(ROW_BYTES), "r"(bar) : "memory");
        }
    }

    // Zero staged-row pads (72 floats/row, disjoint from TMA destinations)
    for (int v = tid; v < STAGE_ROWS * (LPAD + RPAD); v += 256) {
        int r = v / (LPAD + RPAD);
        int p = v % (LPAD + RPAD);
        int idx = (p < LPAD) ? p : (LPAD + N_DIM + (p - LPAD));
        sm[r * RSTRIDE + idx] = 0.0f;
    }
    // Zero out-of-bounds staged rows (only first/last group of each image)
    #pragma unroll
    for (int r = 0; r < STAGE_ROWS; r++) {
        int g = g0 + r;
        if (g < 0 || g >= M_DIM) {
            for (int c = tid; c < N_DIM / 4; c += 256)
                reinterpret_cast<float4*>(sm + r * RSTRIDE + LPAD)[c] =
                    make_float4(0.0f, 0.0f, 0.0f, 0.0f);
        }
    }
    __syncthreads();   // publishes pad stores + mbarrier init to all threads

    // Wait for all bulk copies (acquire orders subsequent LDS after TMA writes)
    {
        uint32_t done;
        do {
            asm volatile(
                "{\n\t.reg .pred p;\n\t"
                "mbarrier.try_wait.parity.acquire.cta.shared::cta.b64 p, [%1], %2;\n\t"
                "selp.b32 %0, 1, 0, p;\n\t}"
                : "=r"(done) : "r"(bar), "r"(0u) : "memory");
        } while (!done);
    }

    // ── Vertical pre-blend: one padded row per output row, fully vectorized ──
    #pragma unroll
    for (int r = 0; r < ROWS_PER_BLK; r++) {
        const int y = ybase + r;
        float yl  = 2.0f * (float)y / (float)(M_DIM - 1) - 1.0f;
        float iy  = ((yl + 1.0f) * (float)M_DIM - 1.0f) * 0.5f;
        float y0f = floorf(iy);
        float wy1 = iy - y0f;
        int   r0  = (int)y0f - g0;               // in [0, 1]

        const float4* __restrict__ a = reinterpret_cast<const float4*>(sm + r0 * RSTRIDE);
        const float4* __restrict__ b = reinterpret_cast<const float4*>(sm + (r0 + 1) * RSTRIDE);
        float4* __restrict__ dst = reinterpret_cast<float4*>(sm + BL_OFF + r * RSTRIDE);

        for (int c = tid; c < VEC_PER_ROW; c += 256) {
            float4 va = a[c], vb = b[c], o;
            o.x = fmaf(wy1, vb.x - va.x, va.x);
            o.y = fmaf(wy1, vb.y - va.y, va.y);
            o.z = fmaf(wy1, vb.z - va.z, va.z);
            o.w = fmaf(wy1, vb.w - va.w, va.w);
            dst[c] = o;
        }
    }
    __syncthreads();

    // ── Gather: lr from smem (coalesced LDS.128) + 2 random scalar taps ──
    const int   xs  = tid * 4;
    const float xlb = (float)xs;
    const float RCP_SCALE = 2.0f / 1023.0f;

    #pragma unroll
    for (int r = 0; r < ROWS_PER_BLK; r++) {
        const int y = ybase + r;
        const float* __restrict__ rowb = sm + BL_OFF + r * RSTRIDE;

        float4 dv = *reinterpret_cast<const float4*>(sm + LR_OFF + r * N_DIM + xs);
        float dd[4] = {dv.x, dv.y, dv.z, dv.w};
        float res[4];

        #pragma unroll
        for (int j = 0; j < 4; j++) {
            float d  = dd[j];
            float xr = (xlb + (float)j) - d;

            float t   = fmaf(xr, RCP_SCALE, -1.0f);   // xr_normed
            float ix  = fmaf(t, 512.0f, 511.5f);      // ((t+1)*1024 - 1)*0.5
            float x0f = floorf(ix);
            float wx1 = ix - x0f;
            int   idx = (int)x0f + LPAD;              // in [3, 1092]; pads absorb OOB

            float b0 = rowb[idx];
            float b1 = rowb[idx + 1];
            float warped = fmaf(wx1, b1 - b0, b0);

            float dist = fabsf(d + warped);
            // d in [0,64) => xr = x-d <= 1023 < N always; only left OOB possible
            res[j] = (xr < 0.0f) ? INVALID_VAL : dist;
        }

        *reinterpret_cast<float4*>(out + sbase + y * N_DIM + xs) =
            make_float4(res[0], res[1], res[2], res[3]);
    }
}

extern "C" void kernel_launch(void* const* d_in, const int* in_sizes, int n_in,
                              void* d_out, int out_size)
{
    const float* lr = (const float*)d_in[0];
    const float* rl = (const float*)d_in[1];
    float* out = (float*)d_out;

    int blocks = S_DIM * (M_DIM / ROWS_PER_BLK);   // 16 * 384 = 6144
    lr_distance_kernel<<<blocks, 256>>>(lr, rl, out);
}